// round 11
// baseline (speedup 1.0000x reference)
#include <cuda_runtime.h>
#include <cuda_bf16.h>
#include <cstdint>

// Problem constants (fixed by the reference)
#define B_ 8
#define S_ 8192
#define H_ 512
#define D_ 768
#define P_ 128
#define M_ (B_ * P_)     // 1024
#define K2_ (H_ / 2)     // 256 packed bf16x2 words per k-row
#define GRID 128
#define NTHR 512

// Scratch (no allocations allowed), packed bf16x2 (k even low, k odd high)
__device__ __align__(16) uint32_t g_Ah[M_ * K2_];    // A hi  [m][k2]
__device__ __align__(16) uint32_t g_Al[M_ * K2_];    // A lo  [m][k2]
__device__ __align__(16) uint32_t g_Wh[K2_ * D_];    // W hi  [k2][n]
__device__ __align__(16) uint32_t g_Wl[K2_ * D_];    // W lo  [k2][n]
__device__ unsigned g_bar;                           // monotonic ticket barrier

__device__ __forceinline__ uint32_t bf16pack(float even_e, float odd_e) {
    uint32_t r;   // low 16 = even k, high 16 = odd k
    asm("cvt.rn.bf16x2.f32 %0, %1, %2;" : "=r"(r) : "f"(odd_e), "f"(even_e));
    return r;
}

__device__ __forceinline__ void bsplit(float v, float& h, float& l) {
    h = __bfloat162float(__float2bfloat16_rn(v));
    l = v - h;
}

__device__ __forceinline__ void wsplit_one(const float* __restrict__ W, int idx) {
    const int k2 = idx / D_;
    const int n  = idx - k2 * D_;
    const float w0 = W[(size_t)(2 * k2) * D_ + n];
    const float w1 = W[(size_t)(2 * k2 + 1) * D_ + n];
    float h0, l0, h1, l1;
    bsplit(w0, h0, l0); bsplit(w1, h1, l1);
    g_Wh[idx] = bf16pack(h0, h1);
    g_Wl[idx] = bf16pack(l0, l1);
}

__device__ __forceinline__ uint32_t smem_u32(const void* p) {
    uint32_t a;
    asm("{ .reg .u64 t; cvta.to.shared.u64 t, %1; cvt.u32.u64 %0, t; }"
        : "=r"(a) : "l"(p));
    return a;
}

__device__ __forceinline__ void cp16(uint32_t saddr, const void* gaddr) {
    asm volatile("cp.async.cg.shared.global [%0], [%1], 16;"
                 :: "r"(saddr), "l"(gaddr));
}

__device__ __forceinline__ void mma_bf16(float* c, const uint32_t* a,
                                         uint32_t b0, uint32_t b1) {
    asm volatile(
        "mma.sync.aligned.m16n8k16.row.col.f32.bf16.bf16.f32 "
        "{%0,%1,%2,%3}, {%4,%5,%6,%7}, {%8,%9}, {%0,%1,%2,%3};"
        : "+f"(c[0]), "+f"(c[1]), "+f"(c[2]), "+f"(c[3])
        : "r"(a[0]), "r"(a[1]), "r"(a[2]), "r"(a[3]), "r"(b0), "r"(b1));
}

// GEMM tiling (R8-proven): block 64x96, BK=64, 16 warps 4m x 4n
#define BM 64
#define BN 96
#define BK 64
#define BK2 (BK / 2)

#define BUFW  11264
#define AHOF  0
#define ALOF  2304
#define WHOF  4608
#define WLOF  7936
#define ASTR  36
#define WSTR  104

// ---------------------------------------------------------------------------
// Fused kernel: phase 1 pool (+W split) -> global barrier -> phase 2 gemm.
// grid = 128 CTAs x 512 threads; all CTAs co-resident (1/SM) -> barrier safe.
// ---------------------------------------------------------------------------
__global__ __launch_bounds__(NTHR, 1)
void fused_kernel(const float* __restrict__ x,
                  const float* __restrict__ W,
                  const float* __restrict__ bias,
                  const int*   __restrict__ pids,
                  float*       __restrict__ out) {
    extern __shared__ uint32_t smw[];
    const uint32_t sb = smem_u32(smw);
    const int c = blockIdx.x;            // 0..127
    const int t = threadIdx.x;           // 0..511

    // ================= Phase 1: pool 8 patches + W split =================
    {
        // W split/pack: 196608 words over 65536 threads = 3 each
        const int gt = c * NTHR + t;
#pragma unroll
        for (int i = 0; i < 3; ++i) wsplit_one(W, gt + i * 65536);

        const int b  = c >> 4;                    // batch row
        const int pb = (c & 15) * 8;              // first patch
        const int* row = pids + (size_t)b * S_;

        int*    sbnd = (int*)smw;                 // 9 boundaries
        float4* part = (float4*)(smw + 16);       // [3][128] partials

        if (t < 9) {                              // 9 parallel binary searches
            const int tgt = pb + t;
            int lo = 0, hi = S_;
            while (lo < hi) {
                int m = (lo + hi) >> 1;
                if (__ldg(row + m) < tgt) lo = m + 1; else hi = m;
            }
            sbnd[t] = lo;
        }
        __syncthreads();

        const int col = t & 127;                  // float4 column
        const int sub = t >> 7;                   // token subset 0..3
        const float4* xp = (const float4*)x + (size_t)b * S_ * (H_ / 4) + col;

        for (int i = 0; i < 8; ++i) {
            const int s0 = sbnd[i], s1 = sbnd[i + 1];
            float4 a0 = make_float4(0.f,0.f,0.f,0.f), a1 = a0, a2 = a0, a3 = a0;

            int s = s0 + sub;
            for (; s + 12 < s1; s += 16) {        // 4 outstanding loads
                const float4 v0 = __ldcs(&xp[(size_t)(s     ) * (H_ / 4)]);
                const float4 v1 = __ldcs(&xp[(size_t)(s +  4) * (H_ / 4)]);
                const float4 v2 = __ldcs(&xp[(size_t)(s +  8) * (H_ / 4)]);
                const float4 v3 = __ldcs(&xp[(size_t)(s + 12) * (H_ / 4)]);
                a0.x += v0.x; a0.y += v0.y; a0.z += v0.z; a0.w += v0.w;
                a1.x += v1.x; a1.y += v1.y; a1.z += v1.z; a1.w += v1.w;
                a2.x += v2.x; a2.y += v2.y; a2.z += v2.z; a2.w += v2.w;
                a3.x += v3.x; a3.y += v3.y; a3.z += v3.z; a3.w += v3.w;
            }
            for (; s < s1; s += 4) {
                const float4 v = __ldcs(&xp[(size_t)s * (H_ / 4)]);
                a0.x += v.x; a0.y += v.y; a0.z += v.z; a0.w += v.w;
            }
            a0.x += a1.x; a0.y += a1.y; a0.z += a1.z; a0.w += a1.w;
            a2.x += a3.x; a2.y += a3.y; a2.z += a3.z; a2.w += a3.w;
            a0.x += a2.x; a0.y += a2.y; a0.z += a2.z; a0.w += a2.w;

            if (sub) part[(sub - 1) * 128 + col] = a0;
            __syncthreads();
            if (sub == 0) {
                const float4 p0 = part[col];
                const float4 p1 = part[128 + col];
                const float4 p2 = part[256 + col];
                const int   cnt = s1 - s0;
                const float rc  = cnt ? (1.0f / (float)cnt) : 0.0f;  // max(cnt,1)
                const float m0v = (a0.x + p0.x + p1.x + p2.x) * rc;
                const float m1v = (a0.y + p0.y + p1.y + p2.y) * rc;
                const float m2v = (a0.z + p0.z + p1.z + p2.z) * rc;
                const float m3v = (a0.w + p0.w + p1.w + p2.w) * rc;

                float h0,l0,h1,l1,h2,l2,h3,l3;
                bsplit(m0v,h0,l0); bsplit(m1v,h1,l1);
                bsplit(m2v,h2,l2); bsplit(m3v,h3,l3);

                const size_t base = (size_t)(c * 8 + i) * K2_ + col * 2;
                uint2 vh, vl;
                vh.x = bf16pack(h0, h1); vh.y = bf16pack(h2, h3);
                vl.x = bf16pack(l0, l1); vl.y = bf16pack(l2, l3);
                *reinterpret_cast<uint2*>(g_Ah + base) = vh;
                *reinterpret_cast<uint2*>(g_Al + base) = vl;
            }
            __syncthreads();
        }
    }

    // ================= Global barrier (monotonic ticket, replay-safe) =====
    if (t == 0) {
        __threadfence();
        const unsigned ticket = atomicAdd(&g_bar, 1u);
        const unsigned target = (ticket / GRID + 1u) * GRID;
        volatile unsigned* vb = &g_bar;
        while (*vb < target) { __nanosleep(64); }
        __threadfence();
    }
    __syncthreads();

    // ================= Phase 2: gemm (R8 body) ===========================
    {
        const int w  = t >> 5;
        const int ln = t & 31;
        const int g  = ln >> 2;
        const int tg = ln & 3;
        const int wm = w & 3;
        const int wn = w >> 2;
        const int m0 = (c >> 3) * BM;
        const int n0 = (c & 7) * BN;

        const int ar  = t >> 3;
        const int aju = t & 7;

        float acc[3][4] = {};

        auto load_chunk = [&](int ch) {
            const int kb2 = ch * BK2;
            {
                const uint32_t so = (ar * ASTR + aju * 4) * 4;
                const size_t  go = (size_t)(m0 + ar) * K2_ + kb2 + aju * 4;
                cp16(sb + ((ch & 1) * BUFW + AHOF) * 4 + so, g_Ah + go);
                cp16(sb + ((ch & 1) * BUFW + ALOF) * 4 + so, g_Al + go);
            }
            {
                const int r = t / 24, cb = t % 24;
                const uint32_t so = (r * WSTR + cb * 4) * 4;
                const size_t  go = (size_t)(kb2 + r) * D_ + n0 + cb * 4;
                cp16(sb + ((ch & 1) * BUFW + WHOF) * 4 + so, g_Wh + go);
                cp16(sb + ((ch & 1) * BUFW + WLOF) * 4 + so, g_Wl + go);
            }
            if (t < 256) {
                const int i2 = t + 512;
                const int r = i2 / 24, cb = i2 % 24;
                const uint32_t so = (r * WSTR + cb * 4) * 4;
                const size_t  go = (size_t)(kb2 + r) * D_ + n0 + cb * 4;
                cp16(sb + ((ch & 1) * BUFW + WHOF) * 4 + so, g_Wh + go);
                cp16(sb + ((ch & 1) * BUFW + WLOF) * 4 + so, g_Wl + go);
            }
        };

        load_chunk(0);
        asm volatile("cp.async.commit_group;" ::: "memory");

        const int NCH = H_ / BK;         // 8
        for (int ch = 0; ch < NCH; ++ch) {
            if (ch + 1 < NCH) {
                load_chunk(ch + 1);
                asm volatile("cp.async.commit_group;" ::: "memory");
                asm volatile("cp.async.wait_group 1;" ::: "memory");
            } else {
                asm volatile("cp.async.wait_group 0;" ::: "memory");
            }
            __syncthreads();

            const uint32_t* Ah = smw + (ch & 1) * BUFW + AHOF;
            const uint32_t* Al = smw + (ch & 1) * BUFW + ALOF;
            const uint32_t* Wh = smw + (ch & 1) * BUFW + WHOF;
            const uint32_t* Wl = smw + (ch & 1) * BUFW + WLOF;
            const int r = wm * 16 + g;

#pragma unroll
            for (int sl = 0; sl < 4; ++sl) {
                const int cc = sl * 8 + tg;
                uint32_t ah[4], al[4];
                ah[0] = Ah[r * ASTR + cc];           al[0] = Al[r * ASTR + cc];
                ah[1] = Ah[(r + 8) * ASTR + cc];     al[1] = Al[(r + 8) * ASTR + cc];
                ah[2] = Ah[r * ASTR + cc + 4];       al[2] = Al[r * ASTR + cc + 4];
                ah[3] = Ah[(r + 8) * ASTR + cc + 4]; al[3] = Al[(r + 8) * ASTR + cc + 4];
#pragma unroll
                for (int nf = 0; nf < 3; ++nf) {
                    const int n = wn * 24 + nf * 8 + g;
                    const uint32_t bh0 = Wh[cc * WSTR + n];
                    const uint32_t bh1 = Wh[(cc + 4) * WSTR + n];
                    const uint32_t bl0 = Wl[cc * WSTR + n];
                    const uint32_t bl1 = Wl[(cc + 4) * WSTR + n];
                    mma_bf16(acc[nf], ah, bh0, bh1);   // hi*hi
                    mma_bf16(acc[nf], al, bh0, bh1);   // lo*hi
                    mma_bf16(acc[nf], ah, bl0, bl1);   // hi*lo
                }
            }
            __syncthreads();
        }

#pragma unroll
        for (int nf = 0; nf < 3; ++nf) {
            const int ncol = n0 + wn * 24 + nf * 8 + 2 * tg;
            const float2 bv = *(const float2*)(bias + ncol);
            const int mrow = m0 + wm * 16 + g;
            float2 o0, o1;
            o0.x = acc[nf][0] + bv.x;  o0.y = acc[nf][1] + bv.y;
            o1.x = acc[nf][2] + bv.x;  o1.y = acc[nf][3] + bv.y;
            *(float2*)(out + (size_t)mrow * D_ + ncol)       = o0;
            *(float2*)(out + (size_t)(mrow + 8) * D_ + ncol) = o1;
        }
    }
}

// ---------------------------------------------------------------------------
// Launch
// ---------------------------------------------------------------------------
extern "C" void kernel_launch(void* const* d_in, const int* in_sizes, int n_in,
                              void* d_out, int out_size) {
    const float* x    = (const float*)d_in[0];   // byte_hiddens [B,S,H]
    const float* W    = (const float*)d_in[1];   // W_proj [H,D]
    const float* bias = (const float*)d_in[2];   // b_proj [D]
    const int*   pids = (const int*)  d_in[3];   // patch_ids [B,S]
    float*       out  = (float*)d_out;           // [B,P,D]

    const int smem_bytes = 2 * BUFW * 4;         // 90112
    cudaFuncSetAttribute(fused_kernel, cudaFuncAttributeMaxDynamicSharedMemorySize,
                         smem_bytes);

    fused_kernel<<<GRID, NTHR, smem_bytes>>>(x, W, bias, pids, out);
}